// round 1
// baseline (speedup 1.0000x reference)
#include <cuda_runtime.h>
#include <cstdint>

#define B_   128
#define T_   1024
#define RNN_ 1024
#define EMB_ 512
#define ATT_ 128
#define NF_  32
#define KS_  31
#define PAD_ 15
#define TILE_ 128          // t-tile for energies kernel
#define NTILES_ (T_ / TILE_)   // 8

// ---------------- scratch (no allocations allowed) ----------------
__device__ float g_pq[B_ * ATT_];                  // 64 KB
__device__ float g_energies[B_ * T_];              // 512 KB
__device__ float g_partial[B_ * NTILES_ * EMB_];   // 2 MB

// ---------------- helpers ----------------
__device__ __forceinline__ float tanh_fast(float x) {
    float y;
    asm("tanh.approx.f32 %0, %1;" : "=f"(y) : "f"(x));
    return y;
}

// ================= K1: pq[b,a] = hidden[b,:] @ w_query[:,a] =================
__global__ void pq_kernel(const float* __restrict__ hidden,
                          const float* __restrict__ wq) {
    __shared__ float s_h[RNN_];
    int b = blockIdx.x;
    int a = threadIdx.x;          // 128 threads
    const float* hrow = hidden + (size_t)b * RNN_;
    #pragma unroll
    for (int r = 0; r < RNN_ / 128; ++r) s_h[a + r * 128] = hrow[a + r * 128];
    __syncthreads();

    float acc = 0.f;
    #pragma unroll 8
    for (int k = 0; k < RNN_; ++k)
        acc = fmaf(s_h[k], wq[(size_t)k * ATT_ + a], acc);
    g_pq[b * ATT_ + a] = acc;
}

// ============ K2: fused conv -> loc -> tanh -> energies ============
// grid (NTILES_, B_), 256 threads
__global__ __launch_bounds__(256) void energies_kernel(
    const float* __restrict__ aw,          // [B,2,T]
    const float* __restrict__ pmem,        // [B,T,ATT]
    const float* __restrict__ wconv,       // [NF,2,KS]
    const float* __restrict__ wloc,        // [NF,ATT]
    const float* __restrict__ vvec)        // [ATT]
{
    __shared__ float s_aw[2 * (TILE_ + KS_ - 1)];     // 2*158
    __shared__ float s_wconv[NF_ * 2 * KS_];          // 1984
    __shared__ float s_wloc[NF_ * ATT_];              // 4096 (float4 friendly)
    __shared__ float s_conv[NF_ * TILE_];             // 4096
    __shared__ float s_pq[ATT_];
    __shared__ float s_v[ATT_];

    const int b  = blockIdx.y;
    const int t0 = blockIdx.x * TILE_;
    const int tid = threadIdx.x;
    const int AWW = TILE_ + KS_ - 1;   // 158

    // ---- loads ----
    for (int idx = tid; idx < 2 * AWW; idx += 256) {
        int i = idx / AWW, j = idx % AWW;
        int gt = t0 + j - PAD_;
        s_aw[idx] = (gt >= 0 && gt < T_) ? aw[((size_t)b * 2 + i) * T_ + gt] : 0.f;
    }
    for (int idx = tid; idx < NF_ * 2 * KS_; idx += 256) s_wconv[idx] = wconv[idx];
    for (int idx = tid; idx < NF_ * ATT_;  idx += 256) s_wloc[idx]  = wloc[idx];
    if (tid < ATT_) { s_pq[tid] = g_pq[b * ATT_ + tid]; s_v[tid] = vvec[tid]; }
    __syncthreads();

    // ---- conv: 32 filters x 128 t, each thread 16 outputs ----
    #pragma unroll
    for (int r = 0; r < 16; ++r) {
        int pos = tid + r * 256;
        int f = pos >> 7, t = pos & 127;
        const float* wc = &s_wconv[f * (2 * KS_)];
        float acc = 0.f;
        #pragma unroll
        for (int k = 0; k < KS_; ++k) acc = fmaf(s_aw[t + k], wc[k], acc);
        #pragma unroll
        for (int k = 0; k < KS_; ++k) acc = fmaf(s_aw[AWW + t + k], wc[KS_ + k], acc);
        s_conv[f * TILE_ + t] = acc;
    }
    __syncthreads();

    // ---- energies: warp per group of 16 t's, lanes split ATT into float4 ----
    const int w = tid >> 5, l = tid & 31;
    const float4* pmem4  = (const float4*)pmem;
    const float4* wloc4  = (const float4*)s_wloc;
    const float4 pq4 = ((const float4*)s_pq)[l];
    const float4 vv4 = ((const float4*)s_v)[l];

    for (int tt = 0; tt < 16; ++tt) {
        const int t  = w * 16 + tt;
        const int gt = t0 + t;
        float4 acc = pmem4[((size_t)b * T_ + gt) * (ATT_ / 4) + l];
        acc.x += pq4.x; acc.y += pq4.y; acc.z += pq4.z; acc.w += pq4.w;

        const float* cp = &s_conv[t];
        #pragma unroll
        for (int f = 0; f < NF_; ++f) {
            float c = cp[f * TILE_];
            float4 wl = wloc4[f * (ATT_ / 4) + l];
            acc.x = fmaf(c, wl.x, acc.x);
            acc.y = fmaf(c, wl.y, acc.y);
            acc.z = fmaf(c, wl.z, acc.z);
            acc.w = fmaf(c, wl.w, acc.w);
        }
        float e = tanh_fast(acc.x) * vv4.x + tanh_fast(acc.y) * vv4.y
                + tanh_fast(acc.z) * vv4.z + tanh_fast(acc.w) * vv4.w;
        #pragma unroll
        for (int o = 16; o; o >>= 1) e += __shfl_xor_sync(0xffffffffu, e, o);
        if (l == 0) g_energies[(size_t)b * T_ + gt] = e;
    }
}

// ================= K3: softmax over T per row, write weights =================
__global__ __launch_bounds__(1024) void softmax_kernel(
    const unsigned char* __restrict__ mask,   // [B,T] (byte view; all-false)
    float* __restrict__ out_w)                // d_out + B*EMB
{
    __shared__ float s_red[32];
    const int b = blockIdx.x, t = threadIdx.x;
    const int w = t >> 5, l = t & 31;

    float e = g_energies[(size_t)b * T_ + t];
    if (mask[(size_t)b * T_ + t]) e = -__int_as_float(0x7f800000); // -inf

    // block max
    float m = e;
    #pragma unroll
    for (int o = 16; o; o >>= 1) m = fmaxf(m, __shfl_xor_sync(0xffffffffu, m, o));
    if (l == 0) s_red[w] = m;
    __syncthreads();
    if (w == 0) {
        float mm = s_red[l];
        #pragma unroll
        for (int o = 16; o; o >>= 1) mm = fmaxf(mm, __shfl_xor_sync(0xffffffffu, mm, o));
        if (l == 0) s_red[0] = mm;
    }
    __syncthreads();
    m = s_red[0];
    __syncthreads();

    float p = expf(e - m);
    // block sum
    float s = p;
    #pragma unroll
    for (int o = 16; o; o >>= 1) s += __shfl_xor_sync(0xffffffffu, s, o);
    if (l == 0) s_red[w] = s;
    __syncthreads();
    if (w == 0) {
        float ss = s_red[l];
        #pragma unroll
        for (int o = 16; o; o >>= 1) ss += __shfl_xor_sync(0xffffffffu, ss, o);
        if (l == 0) s_red[0] = ss;
    }
    __syncthreads();
    s = s_red[0];

    out_w[(size_t)b * T_ + t] = p / s;
}

// ============ K4: context partial sums: grid (NTILES_, B_), 128 thr ============
__global__ __launch_bounds__(128) void context_partial_kernel(
    const float* __restrict__ memory,   // [B,T,EMB]
    const float* __restrict__ out_w)    // weights [B,T]
{
    const int c = blockIdx.x, b = blockIdx.y, d4 = threadIdx.x; // d4 in [0,128)
    const float4* mem4 = (const float4*)memory;
    const float* wrow = out_w + (size_t)b * T_ + c * TILE_;

    float4 acc = make_float4(0.f, 0.f, 0.f, 0.f);
    #pragma unroll 4
    for (int j = 0; j < TILE_; ++j) {
        float wt = __ldg(wrow + j);
        float4 mv = mem4[((size_t)b * T_ + c * TILE_ + j) * (EMB_ / 4) + d4];
        acc.x = fmaf(wt, mv.x, acc.x);
        acc.y = fmaf(wt, mv.y, acc.y);
        acc.z = fmaf(wt, mv.z, acc.z);
        acc.w = fmaf(wt, mv.w, acc.w);
    }
    ((float4*)g_partial)[((size_t)b * NTILES_ + c) * (EMB_ / 4) + d4] = acc;
}

// ================= K5: reduce partials -> context =================
__global__ __launch_bounds__(128) void context_reduce_kernel(float* __restrict__ out) {
    const int b = blockIdx.x, d4 = threadIdx.x;
    const float4* p4 = (const float4*)g_partial;
    float4 s = make_float4(0.f, 0.f, 0.f, 0.f);
    #pragma unroll
    for (int c = 0; c < NTILES_; ++c) {
        float4 v = p4[((size_t)b * NTILES_ + c) * (EMB_ / 4) + d4];
        s.x += v.x; s.y += v.y; s.z += v.z; s.w += v.w;
    }
    ((float4*)out)[(size_t)b * (EMB_ / 4) + d4] = s;
}

// ============================ launch ============================
extern "C" void kernel_launch(void* const* d_in, const int* in_sizes, int n_in,
                              void* d_out, int out_size) {
    const float* hidden = (const float*)d_in[0];                 // [B,RNN]
    const float* memory = (const float*)d_in[1];                 // [B,T,EMB]
    const float* pmem   = (const float*)d_in[2];                 // [B,T,ATT]
    const float* awcat  = (const float*)d_in[3];                 // [B,2,T]
    const unsigned char* mask = (const unsigned char*)d_in[4];   // [B,T] bool
    const float* wq     = (const float*)d_in[5];                 // [RNN,ATT]
    const float* wconv  = (const float*)d_in[6];                 // [NF,2,KS]
    const float* wloc   = (const float*)d_in[7];                 // [NF,ATT]
    const float* vvec   = (const float*)d_in[8];                 // [ATT]

    float* out   = (float*)d_out;
    float* out_w = out + (size_t)B_ * EMB_;   // weights region after context

    pq_kernel<<<B_, 128>>>(hidden, wq);
    energies_kernel<<<dim3(NTILES_, B_), 256>>>(awcat, pmem, wconv, wloc, vvec);
    softmax_kernel<<<B_, T_>>>(mask, out_w);
    context_partial_kernel<<<dim3(NTILES_, B_), 128>>>(memory, out_w);
    context_reduce_kernel<<<B_, 128>>>(out);
}

// round 2
// speedup vs baseline: 1.5904x; 1.5904x over previous
#include <cuda_runtime.h>
#include <cstdint>

#define B_    128
#define T_    1024
#define RNN_  1024
#define EMB_  512
#define ATT_  128
#define NF_   32
#define KS_   31
#define PAD_  15
#define ETILE_ 128            // t-tile for energies kernel
#define ENT_   (T_ / ETILE_)  // 8
#define CTILE_ 64             // t-tile for context kernel
#define CNT_   (T_ / CTILE_)  // 16
#define CONVS_ 132            // padded s_conv row stride (bank-friendly, 16B-mult)

typedef unsigned long long ull;

// ---------------- scratch (no allocations allowed) ----------------
__device__ float g_pq[B_ * ATT_];                 // 64 KB
__device__ float g_energies[B_ * T_];             // 512 KB
__device__ float g_partial[B_ * CNT_ * EMB_];     // 4 MB

// ---------------- helpers ----------------
__device__ __forceinline__ float tanh_fast(float x) {
    float y; asm("tanh.approx.f32 %0, %1;" : "=f"(y) : "f"(x)); return y;
}
__device__ __forceinline__ ull ffma2(ull a, ull b, ull c) {
    ull d; asm("fma.rn.f32x2 %0, %1, %2, %3;" : "=l"(d) : "l"(a), "l"(b), "l"(c));
    return d;
}
__device__ __forceinline__ ull pack2(float lo, float hi) {
    ull d; asm("mov.b64 %0, {%1, %2};" : "=l"(d) : "f"(lo), "f"(hi)); return d;
}
__device__ __forceinline__ float2 unpack2(ull v) {
    float2 r; asm("mov.b64 {%0, %1}, %2;" : "=f"(r.x), "=f"(r.y) : "l"(v)); return r;
}

// ================= K1: pq[b,a] = hidden[b,:] @ w_query[:,a] =================
__global__ void pq_kernel(const float* __restrict__ hidden,
                          const float* __restrict__ wq) {
    __shared__ float s_h[RNN_];
    int b = blockIdx.x;
    int a = threadIdx.x;          // 128 threads
    const float* hrow = hidden + (size_t)b * RNN_;
    #pragma unroll
    for (int r = 0; r < RNN_ / 128; ++r) s_h[a + r * 128] = hrow[a + r * 128];
    __syncthreads();

    float acc = 0.f;
    #pragma unroll 16
    for (int k = 0; k < RNN_; ++k)
        acc = fmaf(s_h[k], wq[(size_t)k * ATT_ + a], acc);
    g_pq[b * ATT_ + a] = acc;
}

// ============ K2: fused conv -> loc -> tanh -> energies (f32x2 packed) ============
// grid (ENT_, B_), 256 threads
__global__ __launch_bounds__(256, 2) void energies_kernel(
    const float* __restrict__ aw,          // [B,2,T]
    const float* __restrict__ pmem,        // [B,T,ATT]
    const float* __restrict__ wconv,       // [NF,2,KS]
    const float* __restrict__ wloc,        // [NF,ATT]
    const float* __restrict__ vvec)        // [ATT]
{
    __shared__ __align__(16) float s_aw [2][160];          // window, aw[t0+j-PAD]
    __shared__ __align__(16) float s_awB[2][160];          // shifted by +1 (odd pairs)
    __shared__ __align__(16) float s_wconv[NF_ * 2 * KS_]; // [f][ch][k]
    __shared__ __align__(16) float s_conv[NF_ * CONVS_];   // [f][t], padded stride
    __shared__ __align__(16) float s_wloc[NF_ * ATT_];     // [f][a]
    __shared__ __align__(16) float s_pq[ATT_];
    __shared__ __align__(16) float s_v[ATT_];

    const int b   = blockIdx.y;
    const int t0  = blockIdx.x * ETILE_;
    const int tid = threadIdx.x;

    // ---- stage shared ----
    for (int idx = tid; idx < 2 * 160; idx += 256) {
        int ch = idx / 160, j = idx % 160;
        int gt  = t0 + j - PAD_;
        int gt2 = gt + 1;
        const float* row = aw + ((size_t)b * 2 + ch) * T_;
        s_aw [ch][j] = (gt  >= 0 && gt  < T_) ? row[gt]  : 0.f;
        s_awB[ch][j] = (gt2 >= 0 && gt2 < T_) ? row[gt2] : 0.f;
    }
    for (int idx = tid; idx < NF_ * 2 * KS_; idx += 256) s_wconv[idx] = wconv[idx];
    for (int idx = tid; idx < NF_ * ATT_;   idx += 256) s_wloc[idx]  = wloc[idx];
    if (tid < ATT_) { s_pq[tid] = g_pq[b * ATT_ + tid]; s_v[tid] = vvec[tid]; }
    __syncthreads();

    // ---- conv: thread = (filter f, 16 consecutive t), fully packed f32x2 ----
    {
        const int f  = tid >> 3;          // 0..31
        const int tb = (tid & 7) * 16;    // 0,16,...,112
        ull acc2[8];
        #pragma unroll
        for (int i = 0; i < 8; ++i) acc2[i] = 0ull;

        #pragma unroll
        for (int ch = 0; ch < 2; ++ch) {
            // we[j] = {aw[tb+2j], aw[tb+2j+1]},  wo[j] = {aw[tb+2j+1], aw[tb+2j+2]}
            ull we[24], wo[24];
            const ulonglong2* pe = (const ulonglong2*)&s_aw [ch][tb];
            const ulonglong2* po = (const ulonglong2*)&s_awB[ch][tb];
            #pragma unroll
            for (int m = 0; m < 12; ++m) {
                ulonglong2 e = pe[m]; we[2*m] = e.x; we[2*m+1] = e.y;
                ulonglong2 o = po[m]; wo[2*m] = o.x; wo[2*m+1] = o.y;
            }
            const float* wc = &s_wconv[f * (2 * KS_) + ch * KS_];
            #pragma unroll
            for (int k = 0; k < KS_; ++k) {
                float wk = wc[k];
                ull wkk = pack2(wk, wk);
                const int m = k >> 1;
                if ((k & 1) == 0) {
                    #pragma unroll
                    for (int i = 0; i < 8; ++i) acc2[i] = ffma2(wkk, we[m + i], acc2[i]);
                } else {
                    #pragma unroll
                    for (int i = 0; i < 8; ++i) acc2[i] = ffma2(wkk, wo[m + i], acc2[i]);
                }
            }
        }
        #pragma unroll
        for (int i = 0; i < 8; ++i)
            *(ull*)&s_conv[f * CONVS_ + tb + 2 * i] = acc2[i];
    }
    __syncthreads();

    // ---- loc + tanh + energies: warp = 16 t's, lane = a-quad [4l..4l+3] ----
    {
        const int w = tid >> 5, l = tid & 31;
        const float4 pq4 = ((const float4*)s_pq)[l];
        const int tbase = t0 + w * 16;
        const float4* pmem4 = (const float4*)pmem;

        ull a01[16], a23[16];
        #pragma unroll
        for (int tt = 0; tt < 16; ++tt) {
            float4 p = pmem4[((size_t)b * T_ + tbase + tt) * (ATT_ / 4) + l];
            a01[tt] = pack2(p.x + pq4.x, p.y + pq4.y);
            a23[tt] = pack2(p.z + pq4.z, p.w + pq4.w);
        }

        const ulonglong2* wl2 = (const ulonglong2*)s_wloc;
        #pragma unroll 4
        for (int f = 0; f < NF_; ++f) {
            ulonglong2 wl = wl2[f * 32 + l];     // {wl[4l],wl[4l+1]}, {wl[4l+2],wl[4l+3]}
            float c[16];
            #pragma unroll
            for (int j = 0; j < 4; ++j) {
                float4 cv = *(const float4*)&s_conv[f * CONVS_ + w * 16 + 4 * j]; // broadcast
                c[4*j+0] = cv.x; c[4*j+1] = cv.y; c[4*j+2] = cv.z; c[4*j+3] = cv.w;
            }
            #pragma unroll
            for (int tt = 0; tt < 16; ++tt) {
                ull cc = pack2(c[tt], c[tt]);
                a01[tt] = ffma2(cc, wl.x, a01[tt]);
                a23[tt] = ffma2(cc, wl.y, a23[tt]);
            }
        }

        const float4 vv = ((const float4*)s_v)[l];
        #pragma unroll
        for (int tt = 0; tt < 16; ++tt) {
            float2 e01 = unpack2(a01[tt]);
            float2 e23 = unpack2(a23[tt]);
            float e = tanh_fast(e01.x) * vv.x + tanh_fast(e01.y) * vv.y
                    + tanh_fast(e23.x) * vv.z + tanh_fast(e23.y) * vv.w;
            #pragma unroll
            for (int o = 16; o; o >>= 1) e += __shfl_xor_sync(0xffffffffu, e, o);
            if (l == 0) g_energies[(size_t)b * T_ + tbase + tt] = e;
        }
    }
}

// ================= K3: softmax over T per row, write weights =================
__global__ __launch_bounds__(1024) void softmax_kernel(
    const unsigned char* __restrict__ mask,   // [B,T]
    float* __restrict__ out_w)                // d_out + B*EMB
{
    __shared__ float s_red[32];
    const int b = blockIdx.x, t = threadIdx.x;
    const int w = t >> 5, l = t & 31;

    float e = g_energies[(size_t)b * T_ + t];
    if (mask[(size_t)b * T_ + t]) e = -__int_as_float(0x7f800000);

    float m = e;
    #pragma unroll
    for (int o = 16; o; o >>= 1) m = fmaxf(m, __shfl_xor_sync(0xffffffffu, m, o));
    if (l == 0) s_red[w] = m;
    __syncthreads();
    if (w == 0) {
        float mm = s_red[l];
        #pragma unroll
        for (int o = 16; o; o >>= 1) mm = fmaxf(mm, __shfl_xor_sync(0xffffffffu, mm, o));
        if (l == 0) s_red[0] = mm;
    }
    __syncthreads();
    m = s_red[0];
    __syncthreads();

    float p = expf(e - m);
    float s = p;
    #pragma unroll
    for (int o = 16; o; o >>= 1) s += __shfl_xor_sync(0xffffffffu, s, o);
    if (l == 0) s_red[w] = s;
    __syncthreads();
    if (w == 0) {
        float ss = s_red[l];
        #pragma unroll
        for (int o = 16; o; o >>= 1) ss += __shfl_xor_sync(0xffffffffu, ss, o);
        if (l == 0) s_red[0] = ss;
    }
    __syncthreads();
    s = s_red[0];

    out_w[(size_t)b * T_ + t] = p / s;
}

// ============ K4: context partials: grid (CNT_, B_), 128 thr ============
__global__ __launch_bounds__(128) void context_partial_kernel(
    const float* __restrict__ memory,   // [B,T,EMB]
    const float* __restrict__ out_w)    // weights [B,T]
{
    const int c = blockIdx.x, b = blockIdx.y, d4 = threadIdx.x; // d4 in [0,128)
    __shared__ float s_w[CTILE_];
    if (threadIdx.x < CTILE_)
        s_w[threadIdx.x] = out_w[(size_t)b * T_ + c * CTILE_ + threadIdx.x];
    __syncthreads();

    const float4* mem4 = (const float4*)memory + ((size_t)b * T_ + c * CTILE_) * (EMB_ / 4) + d4;
    float4 acc = make_float4(0.f, 0.f, 0.f, 0.f);
    #pragma unroll 8
    for (int j = 0; j < CTILE_; ++j) {
        float wt = s_w[j];
        float4 mv = mem4[(size_t)j * (EMB_ / 4)];
        acc.x = fmaf(wt, mv.x, acc.x);
        acc.y = fmaf(wt, mv.y, acc.y);
        acc.z = fmaf(wt, mv.z, acc.z);
        acc.w = fmaf(wt, mv.w, acc.w);
    }
    ((float4*)g_partial)[((size_t)b * CNT_ + c) * (EMB_ / 4) + d4] = acc;
}

// ================= K5: reduce partials -> context =================
__global__ __launch_bounds__(128) void context_reduce_kernel(float* __restrict__ out) {
    const int b = blockIdx.x, d4 = threadIdx.x;
    const float4* p4 = (const float4*)g_partial;
    float4 s = make_float4(0.f, 0.f, 0.f, 0.f);
    #pragma unroll
    for (int c = 0; c < CNT_; ++c) {
        float4 v = p4[((size_t)b * CNT_ + c) * (EMB_ / 4) + d4];
        s.x += v.x; s.y += v.y; s.z += v.z; s.w += v.w;
    }
    ((float4*)out)[(size_t)b * (EMB_ / 4) + d4] = s;
}

// ============================ launch ============================
extern "C" void kernel_launch(void* const* d_in, const int* in_sizes, int n_in,
                              void* d_out, int out_size) {
    const float* hidden = (const float*)d_in[0];                 // [B,RNN]
    const float* memory = (const float*)d_in[1];                 // [B,T,EMB]
    const float* pmem   = (const float*)d_in[2];                 // [B,T,ATT]
    const float* awcat  = (const float*)d_in[3];                 // [B,2,T]
    const unsigned char* mask = (const unsigned char*)d_in[4];   // [B,T] bool
    const float* wq     = (const float*)d_in[5];                 // [RNN,ATT]
    const float* wconv  = (const float*)d_in[6];                 // [NF,2,KS]
    const float* wloc   = (const float*)d_in[7];                 // [NF,ATT]
    const float* vvec   = (const float*)d_in[8];                 // [ATT]

    float* out   = (float*)d_out;
    float* out_w = out + (size_t)B_ * EMB_;   // weights region after context

    pq_kernel<<<B_, 128>>>(hidden, wq);
    energies_kernel<<<dim3(ENT_, B_), 256>>>(awcat, pmem, wconv, wloc, vvec);
    softmax_kernel<<<B_, T_>>>(mask, out_w);
    context_partial_kernel<<<dim3(CNT_, B_), 128>>>(memory, out_w);
    context_reduce_kernel<<<B_, 128>>>(out);
}